// round 1
// baseline (speedup 1.0000x reference)
#include <cuda_runtime.h>
#include <math.h>

#define BB 512
#define TT 1024
#define DD 46
#define DP 48
#define HH 128
#define G3 384
#define BT (BB*TT)

// Scratch for input projections: [B][T][3H] fp32 = 805 MB (device global, no alloc).
__device__ float g_xproj[(size_t)BT * G3];

// ---------------------------------------------------------------------------
// Phase 1: x_proj[R][j] = sum_d hist[R][d] * W_ih[j][d] + b_ih[j]
// CTA tile: 64 rows x 128 cols, 256 threads, thread tile 4x8, K padded to 48.
// ---------------------------------------------------------------------------
__global__ __launch_bounds__(256) void xproj_kernel(
    const float* __restrict__ hist,
    const float* __restrict__ Wih,
    const float* __restrict__ bih)
{
    __shared__ float hs[64][DP];   // 12 KB input rows (zero-padded K)
    __shared__ float ws[DP][HH];   // 24 KB W tile, k-major, XOR-swizzled

    const int tid = threadIdx.x;
    const int R0 = blockIdx.x * 64;
    const int C0 = blockIdx.y * HH;

    for (int i = tid; i < 64 * DP; i += 256) {
        int r = i / DP, d = i - r * DP;
        hs[r][d] = (d < DD) ? hist[(size_t)(R0 + r) * DD + d] : 0.f;
    }
    // gmem-coalesced read (row-major over (c,k)), swizzled STS (~4-way, one-time)
    for (int i = tid; i < HH * DP; i += 256) {
        int c = i / DP, k = i - c * DP;
        float v = (k < DD) ? Wih[(size_t)(C0 + c) * DD + k] : 0.f;
        ws[k][c ^ (4 * (k & 7))] = v;
    }
    __syncthreads();

    const int cg = tid & 15;   // 16 col groups of 8
    const int rg = tid >> 4;   // 16 row groups of 4
    const int c0 = cg * 8, r0 = rg * 4;

    float acc[4][8];
    #pragma unroll
    for (int c = 0; c < 8; c++) {
        float bv = bih[C0 + c0 + c];
        #pragma unroll
        for (int r = 0; r < 4; r++) acc[r][c] = bv;
    }

    #pragma unroll
    for (int k = 0; k < DP; k += 4) {
        float4 hv[4];
        #pragma unroll
        for (int r = 0; r < 4; r++) hv[r] = *(const float4*)&hs[r0 + r][k];
        #pragma unroll
        for (int kk = 0; kk < 4; kk++) {
            const int kq = k + kk;
            const int sw = 4 * (kq & 7);
            float4 w0 = *(const float4*)&ws[kq][(c0)     ^ sw];
            float4 w1 = *(const float4*)&ws[kq][(c0 + 4) ^ sw];
            float wv[8] = {w0.x, w0.y, w0.z, w0.w, w1.x, w1.y, w1.z, w1.w};
            #pragma unroll
            for (int r = 0; r < 4; r++) {
                float hvv = (kk == 0) ? hv[r].x : (kk == 1) ? hv[r].y
                          : (kk == 2) ? hv[r].z : hv[r].w;
                #pragma unroll
                for (int c = 0; c < 8; c++)
                    acc[r][c] = fmaf(hvv, wv[c], acc[r][c]);
            }
        }
    }

    #pragma unroll
    for (int r = 0; r < 4; r++) {
        size_t base = (size_t)(R0 + r0 + r) * G3 + C0 + c0;
        *(float4*)&g_xproj[base]     = make_float4(acc[r][0], acc[r][1], acc[r][2], acc[r][3]);
        *(float4*)&g_xproj[base + 4] = make_float4(acc[r][4], acc[r][5], acc[r][6], acc[r][7]);
    }
}

// ---------------------------------------------------------------------------
// Phase 2: GRU recurrence. One CTA = 4 batch rows, 384 threads (12 warps).
// W_hh resident in SMEM (192 KB, k-major, swizzled). Thread tile: 2 gate rows
// x 4 batches, k-split x2 (reduced via gh partial arrays in SMEM).
// ---------------------------------------------------------------------------
__global__ __launch_bounds__(384, 1) void gru_kernel(
    const float* __restrict__ Whh,
    const float* __restrict__ bhh,
    const float* __restrict__ h0,
    float* __restrict__ out)
{
    extern __shared__ float smem[];
    float* Wt   = smem;               // [128][384] swizzled: Wt[k*384 + (j ^ 4*(k&7))]
    float* h_s  = Wt + HH * G3;       // [4][128]
    float* gh_s = h_s + 4 * HH;       // [2][4][384] partial gh (k-halves)

    const int tid = threadIdx.x;
    const int bbase = blockIdx.x * 4;

    // W_hh transpose-load (coalesced LDG, ~4-way-conflict STS, one-time)
    for (int i = tid; i < G3 * HH; i += 384) {
        int j = i >> 7, k = i & 127;
        Wt[k * G3 + (j ^ (4 * (k & 7)))] = Whh[i];
    }
    // h0 broadcast to all 4 batches
    for (int i = tid; i < HH; i += 384) {
        float v = h0[i];
        h_s[i] = v; h_s[HH + i] = v; h_s[2 * HH + i] = v; h_s[3 * HH + i] = v;
    }

    const int g  = tid % 192;       // gate-row pair index
    const int kh = tid / 192;       // k-half
    const int j0 = 2 * g;
    const int kbase = kh * 64;
    float bh0 = 0.f, bh1 = 0.f;
    if (kh == 0) { bh0 = bhh[j0]; bh1 = bhh[j0 + 1]; }

    const bool gateThread = (tid < 256);
    const int hid = tid & 127;
    const int b0  = (tid >> 7) & 1;   // handles batches b0 and b0+2
    size_t xb0 = 0, xb1 = 0;
    float cxr0 = 0, cxz0 = 0, cxn0 = 0, cxr1 = 0, cxz1 = 0, cxn1 = 0;
    if (gateThread) {
        xb0 = (size_t)(bbase + b0)     * TT * G3 + hid;
        xb1 = (size_t)(bbase + b0 + 2) * TT * G3 + hid;
        cxr0 = g_xproj[xb0]; cxz0 = g_xproj[xb0 + HH]; cxn0 = g_xproj[xb0 + 2 * HH];
        cxr1 = g_xproj[xb1]; cxz1 = g_xproj[xb1 + HH]; cxn1 = g_xproj[xb1 + 2 * HH];
    }
    __syncthreads();

    const float* Wtk = Wt + (size_t)kbase * G3;

    for (int t = 0; t < TT; t++) {
        // Prefetch next step's x_proj; latency hidden behind the k-loop.
        float nxr0 = 0, nxz0 = 0, nxn0 = 0, nxr1 = 0, nxz1 = 0, nxn1 = 0;
        if (gateThread && (t + 1 < TT)) {
            size_t o0 = xb0 + (size_t)(t + 1) * G3;
            size_t o1 = xb1 + (size_t)(t + 1) * G3;
            nxr0 = g_xproj[o0]; nxz0 = g_xproj[o0 + HH]; nxn0 = g_xproj[o0 + 2 * HH];
            nxr1 = g_xproj[o1]; nxz1 = g_xproj[o1 + HH]; nxn1 = g_xproj[o1 + 2 * HH];
        }

        // gh partial: acc[b][jj], b_hh folded in on k-half 0 only
        float i0 = (kh == 0) ? bh0 : 0.f;
        float i1 = (kh == 0) ? bh1 : 0.f;
        float a[4][2];
        #pragma unroll
        for (int b = 0; b < 4; b++) { a[b][0] = i0; a[b][1] = i1; }

        #pragma unroll
        for (int kq = 0; kq < 64; kq += 4) {
            float4 hv0 = *(const float4*)&h_s[0 * HH + kbase + kq];
            float4 hv1 = *(const float4*)&h_s[1 * HH + kbase + kq];
            float4 hv2 = *(const float4*)&h_s[2 * HH + kbase + kq];
            float4 hv3 = *(const float4*)&h_s[3 * HH + kbase + kq];
            #pragma unroll
            for (int kk = 0; kk < 4; kk++) {
                const int kA = kq + kk;              // (kbase % 8 == 0) -> swizzle uses kA&7
                const int sw = 4 * (kA & 7);
                const float2 w = *(const float2*)&Wtk[(size_t)kA * G3 + (j0 ^ sw)];
                float e0 = (kk == 0) ? hv0.x : (kk == 1) ? hv0.y : (kk == 2) ? hv0.z : hv0.w;
                float e1 = (kk == 0) ? hv1.x : (kk == 1) ? hv1.y : (kk == 2) ? hv1.z : hv1.w;
                float e2 = (kk == 0) ? hv2.x : (kk == 1) ? hv2.y : (kk == 2) ? hv2.z : hv2.w;
                float e3 = (kk == 0) ? hv3.x : (kk == 1) ? hv3.y : (kk == 2) ? hv3.z : hv3.w;
                a[0][0] = fmaf(w.x, e0, a[0][0]); a[0][1] = fmaf(w.y, e0, a[0][1]);
                a[1][0] = fmaf(w.x, e1, a[1][0]); a[1][1] = fmaf(w.y, e1, a[1][1]);
                a[2][0] = fmaf(w.x, e2, a[2][0]); a[2][1] = fmaf(w.y, e2, a[2][1]);
                a[3][0] = fmaf(w.x, e3, a[3][0]); a[3][1] = fmaf(w.y, e3, a[3][1]);
            }
        }

        *(float2*)&gh_s[(kh * 4 + 0) * G3 + j0] = make_float2(a[0][0], a[0][1]);
        *(float2*)&gh_s[(kh * 4 + 1) * G3 + j0] = make_float2(a[1][0], a[1][1]);
        *(float2*)&gh_s[(kh * 4 + 2) * G3 + j0] = make_float2(a[2][0], a[2][1]);
        *(float2*)&gh_s[(kh * 4 + 3) * G3 + j0] = make_float2(a[3][0], a[3][1]);
        __syncthreads();

        if (gateThread) {
            #pragma unroll
            for (int it = 0; it < 2; it++) {
                const int b = b0 + 2 * it;
                const float xr = it ? cxr1 : cxr0;
                const float xz = it ? cxz1 : cxz0;
                const float xn = it ? cxn1 : cxn0;
                float gr = gh_s[b * G3 + hid]          + gh_s[(4 + b) * G3 + hid];
                float gz = gh_s[b * G3 + HH + hid]     + gh_s[(4 + b) * G3 + HH + hid];
                float gn = gh_s[b * G3 + 2 * HH + hid] + gh_s[(4 + b) * G3 + 2 * HH + hid];
                float r = __fdividef(1.f, 1.f + __expf(-(xr + gr)));
                float z = __fdividef(1.f, 1.f + __expf(-(xz + gz)));
                float na = xn + r * gn;
                float ea = __expf(-2.f * fabsf(na));
                float n  = copysignf(__fdividef(1.f - ea, 1.f + ea), na);
                float hold = h_s[b * HH + hid];
                h_s[b * HH + hid] = n + z * (hold - n);
            }
            cxr0 = nxr0; cxz0 = nxz0; cxn0 = nxn0;
            cxr1 = nxr1; cxz1 = nxz1; cxn1 = nxn1;
        }
        __syncthreads();
    }

    if (gateThread) {
        out[(bbase + b0) * HH + hid]       = h_s[b0 * HH + hid];
        out[(bbase + b0 + 2) * HH + hid]   = h_s[(b0 + 2) * HH + hid];
    }
}

extern "C" void kernel_launch(void* const* d_in, const int* in_sizes, int n_in,
                              void* d_out, int out_size) {
    const float* hist = (const float*)d_in[0];
    const float* Wih  = (const float*)d_in[1];
    const float* Whh  = (const float*)d_in[2];
    const float* bih  = (const float*)d_in[3];
    const float* bhh  = (const float*)d_in[4];
    const float* h0   = (const float*)d_in[5];
    float* out = (float*)d_out;

    xproj_kernel<<<dim3(BT / 64, 3), 256>>>(hist, Wih, bih);

    const size_t smem_bytes = (size_t)(HH * G3 + 4 * HH + 8 * G3) * sizeof(float); // 210944
    cudaFuncSetAttribute(gru_kernel, cudaFuncAttributeMaxDynamicSharedMemorySize,
                         (int)smem_bytes);
    gru_kernel<<<BB / 4, 384, smem_bytes>>>(Whh, bhh, h0, out);
}

// round 2
// speedup vs baseline: 1.0555x; 1.0555x over previous
#include <cuda_runtime.h>
#include <math.h>

#define BB 512
#define TT 1024
#define DD 46
#define DP 48
#define HH 128
#define G3 384
#define BT (BB*TT)

// Scratch for input projections: [B][T][3H] fp32 = 805 MB (device global, no alloc).
__device__ float g_xproj[(size_t)BT * G3];

// ---------------------------------------------------------------------------
// Phase 1: x_proj[R][j] = sum_d hist[R][d] * W_ih[j][d] + b_ih[j]
// CTA tile: 64 rows x 384 cols, 256 threads (8 warps).
// Thread tile: 8 rows x 12 cols as 3 lane-interleaved col-quads {q, q+128, q+256}.
// ---------------------------------------------------------------------------
#define HSP 68    // hsT row pad (48 x 68)
#define WSP 388   // ws  row pad (48 x 388)

__global__ __launch_bounds__(256) void xproj_kernel(
    const float* __restrict__ hist,
    const float* __restrict__ Wih,
    const float* __restrict__ bih)
{
    __shared__ float hsT[DP * HSP];   // [k][row]   (transposed, broadcast reads)
    __shared__ float ws[DP * WSP];    // [k][col]

    const int tid = threadIdx.x;
    const int R0 = blockIdx.x * 64;

    // hist -> hsT (coalesced LDG over d, 4-way STS conflicts, one-time)
    for (int i = tid; i < 64 * DP; i += 256) {
        int r = i / DP, d = i - r * DP;
        float v = (d < DD) ? hist[(size_t)(R0 + r) * DD + d] : 0.f;
        hsT[d * HSP + r] = v;
    }
    // W_ih -> ws (coalesced LDG over d, ~4-way STS conflicts, one-time)
    for (int i = tid; i < G3 * DP; i += 256) {
        int c = i / DP, d = i - c * DP;
        float v = (d < DD) ? Wih[(size_t)c * DD + d] : 0.f;
        ws[d * WSP + c] = v;
    }
    __syncthreads();

    const int lane = tid & 31;
    const int warp = tid >> 5;
    const int q0 = lane * 4;     // col quads: q0, q0+128, q0+256
    const int r0 = warp * 8;     // 8 rows

    float acc[8][3][4];
    {
        float4 b0 = *(const float4*)&bih[q0];
        float4 b1 = *(const float4*)&bih[q0 + 128];
        float4 b2 = *(const float4*)&bih[q0 + 256];
        #pragma unroll
        for (int i = 0; i < 8; i++) {
            acc[i][0][0] = b0.x; acc[i][0][1] = b0.y; acc[i][0][2] = b0.z; acc[i][0][3] = b0.w;
            acc[i][1][0] = b1.x; acc[i][1][1] = b1.y; acc[i][1][2] = b1.z; acc[i][1][3] = b1.w;
            acc[i][2][0] = b2.x; acc[i][2][1] = b2.y; acc[i][2][2] = b2.z; acc[i][2][3] = b2.w;
        }
    }

    #pragma unroll 4
    for (int k = 0; k < DP; k++) {
        float4 w0 = *(const float4*)&ws[k * WSP + q0];
        float4 w1 = *(const float4*)&ws[k * WSP + q0 + 128];
        float4 w2 = *(const float4*)&ws[k * WSP + q0 + 256];
        float4 ha = *(const float4*)&hsT[k * HSP + r0];
        float4 hb = *(const float4*)&hsT[k * HSP + r0 + 4];
        float hv[8] = {ha.x, ha.y, ha.z, ha.w, hb.x, hb.y, hb.z, hb.w};
        #pragma unroll
        for (int i = 0; i < 8; i++) {
            float h = hv[i];
            acc[i][0][0] = fmaf(h, w0.x, acc[i][0][0]);
            acc[i][0][1] = fmaf(h, w0.y, acc[i][0][1]);
            acc[i][0][2] = fmaf(h, w0.z, acc[i][0][2]);
            acc[i][0][3] = fmaf(h, w0.w, acc[i][0][3]);
            acc[i][1][0] = fmaf(h, w1.x, acc[i][1][0]);
            acc[i][1][1] = fmaf(h, w1.y, acc[i][1][1]);
            acc[i][1][2] = fmaf(h, w1.z, acc[i][1][2]);
            acc[i][1][3] = fmaf(h, w1.w, acc[i][1][3]);
            acc[i][2][0] = fmaf(h, w2.x, acc[i][2][0]);
            acc[i][2][1] = fmaf(h, w2.y, acc[i][2][1]);
            acc[i][2][2] = fmaf(h, w2.z, acc[i][2][2]);
            acc[i][2][3] = fmaf(h, w2.w, acc[i][2][3]);
        }
    }

    #pragma unroll
    for (int i = 0; i < 8; i++) {
        size_t base = (size_t)(R0 + r0 + i) * G3;
        *(float4*)&g_xproj[base + q0]       = make_float4(acc[i][0][0], acc[i][0][1], acc[i][0][2], acc[i][0][3]);
        *(float4*)&g_xproj[base + q0 + 128] = make_float4(acc[i][1][0], acc[i][1][1], acc[i][1][2], acc[i][1][3]);
        *(float4*)&g_xproj[base + q0 + 256] = make_float4(acc[i][2][0], acc[i][2][1], acc[i][2][2], acc[i][2][3]);
    }
}

// ---------------------------------------------------------------------------
// Phase 2: GRU recurrence. One CTA = 4 batch rows, 768 threads (24 warps).
// Thread = 1 gate row (j) x 4 batches x k-split 2 (kh).
// Each thread's first 32 W values live in REGISTERS (time-invariant!);
// the other 32 come from SMEM (coalesced LDS.32).
// h stored [k][b] so one broadcast LDS.128 feeds 4 batch FFMAs.
// ---------------------------------------------------------------------------
#define WSR 385                      // W_s row pad
#define SM_WS   0                    // W_s:  [64][385]  (k-rows 32..63 and 96..127)
#define SM_HS   (64 * WSR)           // h_s:  [128][4]
#define SM_GH   (SM_HS + HH * 4)     // gh_s: [2][4][384]
#define SM_TOT  (SM_GH + 8 * G3)     // floats

__global__ __launch_bounds__(768, 1) void gru_kernel(
    const float* __restrict__ Whh,
    const float* __restrict__ bhh,
    const float* __restrict__ h0,
    float* __restrict__ out)
{
    extern __shared__ float smem[];
    float* W_s  = smem + SM_WS;
    float* h_s  = smem + SM_HS;
    float* gh_s = smem + SM_GH;

    const int tid = threadIdx.x;
    const int bbase = blockIdx.x * 4;

    const int j  = tid % G3;          // gate row
    const int kh = tid / G3;          // k half
    const int kbase = kh * 64;

    // Register-resident W slice: W[j][kbase .. kbase+32)
    float4 W4[8];
    #pragma unroll
    for (int q = 0; q < 8; q++)
        W4[q] = *(const float4*)&Whh[(size_t)j * HH + kbase + q * 4];

    // SMEM W slice: rows c=0..31 <-> k=32+c, rows c=32..63 <-> k=64+c (=96..127)
    for (int idx = tid; idx < G3 * 64; idx += 768) {
        int jj = idx >> 6, c = idx & 63;
        int k = (c < 32) ? (32 + c) : (64 + c);
        W_s[c * WSR + jj] = Whh[(size_t)jj * HH + k];
    }
    // h0 broadcast over 4 batches, layout h_s[k][b]
    for (int i = tid; i < HH; i += 768) {
        float v = h0[i];
        *(float4*)&h_s[i * 4] = make_float4(v, v, v, v);
    }

    const float bias = (kh == 0) ? bhh[j] : 0.f;

    const bool gateThread = (tid < 512);
    const int hid = tid & 127;
    const int b   = (tid >> 7) & 3;   // batch this gate-thread owns
    const float* xp = nullptr;
    float cxr = 0, cxz = 0, cxn = 0;
    if (gateThread) {
        xp = g_xproj + (size_t)(bbase + b) * TT * G3 + hid;
        cxr = xp[0]; cxz = xp[HH]; cxn = xp[2 * HH];
    }
    __syncthreads();

    for (int t = 0; t < TT; t++) {
        // Prefetch next step's x_proj (latency hidden behind k-loop)
        float nxr = 0, nxz = 0, nxn = 0;
        if (gateThread && (t + 1 < TT)) {
            const float* xn_p = xp + (size_t)(t + 1) * G3;
            nxr = xn_p[0]; nxz = xn_p[HH]; nxn = xn_p[2 * HH];
        }

        float a0 = bias, a1 = bias, a2 = bias, a3 = bias;

        // k in [kbase, kbase+32): W from registers
        #pragma unroll
        for (int i = 0; i < 32; i++) {
            float w = (i % 4 == 0) ? W4[i / 4].x : (i % 4 == 1) ? W4[i / 4].y
                    : (i % 4 == 2) ? W4[i / 4].z : W4[i / 4].w;
            float4 h4 = *(const float4*)&h_s[(kbase + i) * 4];
            a0 = fmaf(w, h4.x, a0); a1 = fmaf(w, h4.y, a1);
            a2 = fmaf(w, h4.z, a2); a3 = fmaf(w, h4.w, a3);
        }
        // k in [kbase+32, kbase+64): W from SMEM (row kh*32+i, coalesced over j)
        #pragma unroll
        for (int i = 0; i < 32; i++) {
            float w = W_s[(kh * 32 + i) * WSR + j];
            float4 h4 = *(const float4*)&h_s[(kbase + 32 + i) * 4];
            a0 = fmaf(w, h4.x, a0); a1 = fmaf(w, h4.y, a1);
            a2 = fmaf(w, h4.z, a2); a3 = fmaf(w, h4.w, a3);
        }

        gh_s[(kh * 4 + 0) * G3 + j] = a0;
        gh_s[(kh * 4 + 1) * G3 + j] = a1;
        gh_s[(kh * 4 + 2) * G3 + j] = a2;
        gh_s[(kh * 4 + 3) * G3 + j] = a3;
        __syncthreads();

        if (gateThread) {
            float gr = gh_s[b * G3 + hid]          + gh_s[(4 + b) * G3 + hid];
            float gz = gh_s[b * G3 + HH + hid]     + gh_s[(4 + b) * G3 + HH + hid];
            float gn = gh_s[b * G3 + 2 * HH + hid] + gh_s[(4 + b) * G3 + 2 * HH + hid];
            float r = __fdividef(1.f, 1.f + __expf(-(cxr + gr)));
            float z = __fdividef(1.f, 1.f + __expf(-(cxz + gz)));
            float na = cxn + r * gn;
            float ea = __expf(-2.f * fabsf(na));
            float n  = copysignf(__fdividef(1.f - ea, 1.f + ea), na);
            float hold = h_s[hid * 4 + b];
            h_s[hid * 4 + b] = n + z * (hold - n);
            cxr = nxr; cxz = nxz; cxn = nxn;
        }
        __syncthreads();
    }

    if (gateThread)
        out[(bbase + b) * HH + hid] = h_s[hid * 4 + b];
}

extern "C" void kernel_launch(void* const* d_in, const int* in_sizes, int n_in,
                              void* d_out, int out_size) {
    const float* hist = (const float*)d_in[0];
    const float* Wih  = (const float*)d_in[1];
    const float* Whh  = (const float*)d_in[2];
    const float* bih  = (const float*)d_in[3];
    const float* bhh  = (const float*)d_in[4];
    const float* h0   = (const float*)d_in[5];
    float* out = (float*)d_out;

    xproj_kernel<<<BT / 64, 256>>>(hist, Wih, bih);

    const size_t smem_bytes = (size_t)SM_TOT * sizeof(float);  // 112,896 B
    cudaFuncSetAttribute(gru_kernel, cudaFuncAttributeMaxDynamicSharedMemorySize,
                         (int)smem_bytes);
    gru_kernel<<<BB / 4, 768, smem_bytes>>>(Whh, bhh, h0, out);
}

// round 4
// speedup vs baseline: 1.3339x; 1.2638x over previous
#include <cuda_runtime.h>
#include <math.h>

#define BB 512
#define TT 1024
#define DD 46
#define DP 48
#define HH 128
#define G3 384
#define BT (BB*TT)

// Scratch for input projections: [B][T][3H] fp32 = 805 MB (device global, no alloc).
__device__ float g_xproj[(size_t)BT * G3];

// ---------------------------------------------------------------------------
// Phase 1: x_proj[R][j] = sum_d hist[R][d] * W_ih[j][d] + b_ih[j]
// CTA tile: 64 rows x 384 cols, 512 threads (16 warps).
// Warp -> 4 rows; thread tile: 4 rows x 12 cols (3 lane-interleaved quads).
// ---------------------------------------------------------------------------
#define HSP 68    // hsT row pad (48 x 68)
#define WSP 388   // ws  row pad (48 x 388)

__global__ __launch_bounds__(512) void xproj_kernel(
    const float* __restrict__ hist,
    const float* __restrict__ Wih,
    const float* __restrict__ bih)
{
    extern __shared__ float xsm[];
    float* hsT = xsm;              // [48][68]  (k-major, broadcast reads)
    float* ws  = xsm + DP * HSP;   // [48][388] (k-major)

    const int tid = threadIdx.x;
    const int R0 = blockIdx.x * 64;

    for (int i = tid; i < 64 * DP; i += 512) {
        int r = i / DP, d = i - r * DP;
        hsT[d * HSP + r] = (d < DD) ? hist[(size_t)(R0 + r) * DD + d] : 0.f;
    }
    for (int i = tid; i < G3 * DP; i += 512) {
        int c = i / DP, d = i - c * DP;
        ws[d * WSP + c] = (d < DD) ? Wih[(size_t)c * DD + d] : 0.f;
    }
    __syncthreads();

    const int lane = tid & 31;
    const int warp = tid >> 5;
    const int q0 = lane * 4;     // col quads: q0, q0+128, q0+256
    const int r0 = warp * 4;     // 4 rows

    float acc[4][3][4];
    {
        float4 b0 = *(const float4*)&bih[q0];
        float4 b1 = *(const float4*)&bih[q0 + 128];
        float4 b2 = *(const float4*)&bih[q0 + 256];
        #pragma unroll
        for (int i = 0; i < 4; i++) {
            acc[i][0][0] = b0.x; acc[i][0][1] = b0.y; acc[i][0][2] = b0.z; acc[i][0][3] = b0.w;
            acc[i][1][0] = b1.x; acc[i][1][1] = b1.y; acc[i][1][2] = b1.z; acc[i][1][3] = b1.w;
            acc[i][2][0] = b2.x; acc[i][2][1] = b2.y; acc[i][2][2] = b2.z; acc[i][2][3] = b2.w;
        }
    }

    #pragma unroll 4
    for (int k = 0; k < DP; k++) {
        float4 w0 = *(const float4*)&ws[k * WSP + q0];
        float4 w1 = *(const float4*)&ws[k * WSP + q0 + 128];
        float4 w2 = *(const float4*)&ws[k * WSP + q0 + 256];
        float4 ha = *(const float4*)&hsT[k * HSP + r0];
        float hv[4] = {ha.x, ha.y, ha.z, ha.w};
        #pragma unroll
        for (int i = 0; i < 4; i++) {
            float h = hv[i];
            acc[i][0][0] = fmaf(h, w0.x, acc[i][0][0]);
            acc[i][0][1] = fmaf(h, w0.y, acc[i][0][1]);
            acc[i][0][2] = fmaf(h, w0.z, acc[i][0][2]);
            acc[i][0][3] = fmaf(h, w0.w, acc[i][0][3]);
            acc[i][1][0] = fmaf(h, w1.x, acc[i][1][0]);
            acc[i][1][1] = fmaf(h, w1.y, acc[i][1][1]);
            acc[i][1][2] = fmaf(h, w1.z, acc[i][1][2]);
            acc[i][1][3] = fmaf(h, w1.w, acc[i][1][3]);
            acc[i][2][0] = fmaf(h, w2.x, acc[i][2][0]);
            acc[i][2][1] = fmaf(h, w2.y, acc[i][2][1]);
            acc[i][2][2] = fmaf(h, w2.z, acc[i][2][2]);
            acc[i][2][3] = fmaf(h, w2.w, acc[i][2][3]);
        }
    }

    #pragma unroll
    for (int i = 0; i < 4; i++) {
        size_t base = (size_t)(R0 + r0 + i) * G3;
        *(float4*)&g_xproj[base + q0]       = make_float4(acc[i][0][0], acc[i][0][1], acc[i][0][2], acc[i][0][3]);
        *(float4*)&g_xproj[base + q0 + 128] = make_float4(acc[i][1][0], acc[i][1][1], acc[i][1][2], acc[i][1][3]);
        *(float4*)&g_xproj[base + q0 + 256] = make_float4(acc[i][2][0], acc[i][2][1], acc[i][2][2], acc[i][2][3]);
    }
}

// ---------------------------------------------------------------------------
// Phase 2: GRU recurrence. One CTA = 4 batch rows, 256 threads (8 warps).
// Thread = 3 gate rows (j0, j0+128, j0+256) x 4 batches, k-split 2.
// Per k: 1 broadcast LDS.128 (h, 4 batches) + 3 coalesced LDS.32 (W) -> 12 FFMA.
// W_hh fully SMEM-resident, k-major [k][j] (conflict-free per-warp reads).
// ---------------------------------------------------------------------------
#define SM_WS   0                    // W_s:  [128][384]
#define SM_HS   (HH * G3)            // h_s:  [128][4]  (k-major over batches)
#define SM_GH   (SM_HS + HH * 4)     // gh_s: [2][4][384] k-half partials
#define SM_TOT  (SM_GH + 8 * G3)     // floats = 52736 (210,944 B)

__global__ __launch_bounds__(256, 1) void gru_kernel(
    const float* __restrict__ Whh,
    const float* __restrict__ bhh,
    const float* __restrict__ h0,
    float* __restrict__ out)
{
    extern __shared__ float smem[];
    float* W_s  = smem + SM_WS;
    float* h_s  = smem + SM_HS;
    float* gh_s = smem + SM_GH;

    const int tid = threadIdx.x;
    const int bbase = blockIdx.x * 4;

    const int j0 = tid & 127;         // gate triple base: rows j0, j0+128, j0+256
    const int kh = tid >> 7;          // k half
    const int kbase = kh * 64;

    // W_hh -> SMEM k-major (one-time; STS conflicts irrelevant at this scale)
    for (int i = tid; i < G3 * HH; i += 256) {
        int j = i >> 7, k = i & 127;
        W_s[k * G3 + j] = Whh[i];
    }
    // h0 broadcast over 4 batches, layout h_s[k][b]
    for (int i = tid; i < HH; i += 256) {
        float v = h0[i];
        *(float4*)&h_s[i * 4] = make_float4(v, v, v, v);
    }

    float bias[3] = {0.f, 0.f, 0.f};
    if (kh == 0) {
        bias[0] = bhh[j0]; bias[1] = bhh[j0 + 128]; bias[2] = bhh[j0 + 256];
    }

    // Gate phase mapping: thread handles (hid = j0) for batches {2*kh, 2*kh+1}
    const int hid = j0;
    const int bg0 = kh * 2;
    const float* xpA = g_xproj + (size_t)(bbase + bg0)     * TT * G3 + hid;
    const float* xpB = g_xproj + (size_t)(bbase + bg0 + 1) * TT * G3 + hid;
    float cxrA = xpA[0], cxzA = xpA[HH], cxnA = xpA[2 * HH];
    float cxrB = xpB[0], cxzB = xpB[HH], cxnB = xpB[2 * HH];
    __syncthreads();

    for (int t = 0; t < TT; t++) {
        // Prefetch next step's x_proj (latency hidden behind k-loop)
        float nxrA = 0, nxzA = 0, nxnA = 0, nxrB = 0, nxzB = 0, nxnB = 0;
        if (t + 1 < TT) {
            const float* pA = xpA + (size_t)(t + 1) * G3;
            const float* pB = xpB + (size_t)(t + 1) * G3;
            nxrA = pA[0]; nxzA = pA[HH]; nxnA = pA[2 * HH];
            nxrB = pB[0]; nxzB = pB[HH]; nxnB = pB[2 * HH];
        }

        float a[3][4];
        #pragma unroll
        for (int g = 0; g < 3; g++) {
            a[g][0] = bias[g]; a[g][1] = bias[g]; a[g][2] = bias[g]; a[g][3] = bias[g];
        }

        #pragma unroll 8
        for (int i = 0; i < 64; i++) {
            const int k = kbase + i;
            float4 h4 = *(const float4*)&h_s[k * 4];
            float w0 = W_s[k * G3 + j0];
            float w1 = W_s[k * G3 + j0 + 128];
            float w2 = W_s[k * G3 + j0 + 256];
            a[0][0] = fmaf(w0, h4.x, a[0][0]); a[0][1] = fmaf(w0, h4.y, a[0][1]);
            a[0][2] = fmaf(w0, h4.z, a[0][2]); a[0][3] = fmaf(w0, h4.w, a[0][3]);
            a[1][0] = fmaf(w1, h4.x, a[1][0]); a[1][1] = fmaf(w1, h4.y, a[1][1]);
            a[1][2] = fmaf(w1, h4.z, a[1][2]); a[1][3] = fmaf(w1, h4.w, a[1][3]);
            a[2][0] = fmaf(w2, h4.x, a[2][0]); a[2][1] = fmaf(w2, h4.y, a[2][1]);
            a[2][2] = fmaf(w2, h4.z, a[2][2]); a[2][3] = fmaf(w2, h4.w, a[2][3]);
        }

        #pragma unroll
        for (int g = 0; g < 3; g++) {
            #pragma unroll
            for (int b = 0; b < 4; b++)
                gh_s[(kh * 4 + b) * G3 + j0 + g * 128] = a[g][b];
        }
        __syncthreads();

        // Gate phase: 256 threads x 2 batches each = 512 (b, hid) items
        #pragma unroll
        for (int it = 0; it < 2; it++) {
            const int b = bg0 + it;
            const float xr = it ? cxrB : cxrA;
            const float xz = it ? cxzB : cxzA;
            const float xn = it ? cxnB : cxnA;
            float gr = gh_s[b * G3 + hid]            + gh_s[(4 + b) * G3 + hid];
            float gz = gh_s[b * G3 + 128 + hid]      + gh_s[(4 + b) * G3 + 128 + hid];
            float gn = gh_s[b * G3 + 256 + hid]      + gh_s[(4 + b) * G3 + 256 + hid];
            float r = __fdividef(1.f, 1.f + __expf(-(xr + gr)));
            float z = __fdividef(1.f, 1.f + __expf(-(xz + gz)));
            float na = xn + r * gn;
            float ea = __expf(-2.f * fabsf(na));
            float n  = copysignf(__fdividef(1.f - ea, 1.f + ea), na);
            float hold = h_s[hid * 4 + b];
            h_s[hid * 4 + b] = n + z * (hold - n);
        }
        cxrA = nxrA; cxzA = nxzA; cxnA = nxnA;
        cxrB = nxrB; cxzB = nxzB; cxnB = nxnB;
        __syncthreads();
    }

    out[(bbase + bg0) * HH + hid]     = h_s[hid * 4 + bg0];
    out[(bbase + bg0 + 1) * HH + hid] = h_s[hid * 4 + bg0 + 1];
}

extern "C" void kernel_launch(void* const* d_in, const int* in_sizes, int n_in,
                              void* d_out, int out_size) {
    const float* hist = (const float*)d_in[0];
    const float* Wih  = (const float*)d_in[1];
    const float* Whh  = (const float*)d_in[2];
    const float* bih  = (const float*)d_in[3];
    const float* bhh  = (const float*)d_in[4];
    const float* h0   = (const float*)d_in[5];
    float* out = (float*)d_out;

    const size_t xsm_bytes = (size_t)(DP * HSP + DP * WSP) * sizeof(float); // 87,552
    cudaFuncSetAttribute(xproj_kernel, cudaFuncAttributeMaxDynamicSharedMemorySize,
                         (int)xsm_bytes);
    xproj_kernel<<<BT / 64, 512, xsm_bytes>>>(hist, Wih, bih);

    const size_t smem_bytes = (size_t)SM_TOT * sizeof(float);  // 210,944 B
    cudaFuncSetAttribute(gru_kernel, cudaFuncAttributeMaxDynamicSharedMemorySize,
                         (int)smem_bytes);
    gru_kernel<<<BB / 4, 256, smem_bytes>>>(Whh, bhh, h0, out);
}

// round 10
// speedup vs baseline: 1.4994x; 1.1241x over previous
#include <cuda_runtime.h>
#include <math.h>

#define BB 512
#define TT 1024
#define DD 46
#define DP 48
#define HH 128
#define G3 384
#define BT (BB*TT)

// Packed 2xFP32 ops (sm_103a). Exact IEEE fp32 per lane.
#define DUP2(d, s)       asm("mov.b64 %0, {%1, %1};" : "=l"(d) : "f"(s))
#define PK2(d, lo, hi)   asm("mov.b64 %0, {%1, %2};" : "=l"(d) : "f"(lo), "f"(hi))
#define UPK2(lo, hi, s)  asm("mov.b64 {%0, %1}, %2;" : "=f"(lo), "=f"(hi) : "l"(s))
#define FMA2(acc, a, b)  asm("fma.rn.f32x2 %0, %1, %2, %0;" : "+l"(acc) : "l"(a), "l"(b))

// Scratch for input projections: [B][T][3H] fp32 = 805 MB (device global, no alloc).
__device__ float g_xproj[(size_t)BT * G3];

// ---------------------------------------------------------------------------
// Phase 1: x_proj[R][j] = sum_d hist[R][d] * W_ih[j][d] + b_ih[j]
// CTA tile: 64 rows x 384 cols, 256 threads (8 warps).
// Thread tile: 8 rows x 12 cols, accumulators packed over column PAIRS (f32x2).
// W pairs come straight out of LDS.128 reinterprets; only h needs dup-movs.
// ---------------------------------------------------------------------------
#define HSP 68    // hsT row pad (48 x 68); 272B row stride (16B aligned)
#define WSP 388   // ws  row pad (48 x 388); 1552B row stride (16B aligned)

__global__ __launch_bounds__(256, 1) void xproj_kernel(
    const float* __restrict__ hist,
    const float* __restrict__ Wih,
    const float* __restrict__ bih)
{
    extern __shared__ float xsm[];
    float* hsT = xsm;              // [48][68]  (k-major)
    float* ws  = xsm + DP * HSP;   // [48][388] (k-major)

    const int tid = threadIdx.x;
    const int R0 = blockIdx.x * 64;

    for (int i = tid; i < 64 * DP; i += 256) {
        int r = i / DP, d = i - r * DP;
        hsT[d * HSP + r] = (d < DD) ? hist[(size_t)(R0 + r) * DD + d] : 0.f;
    }
    for (int i = tid; i < G3 * DP; i += 256) {
        int c = i / DP, d = i - c * DP;
        ws[d * WSP + c] = (d < DD) ? Wih[(size_t)c * DD + d] : 0.f;
    }
    __syncthreads();

    const int lane = tid & 31;
    const int warp = tid >> 5;
    const int q0 = lane * 4;     // col quads: q0, q0+128, q0+256
    const int r0 = warp * 8;     // 8 rows

    // acc[row][pair]: pairs 0,1 <- quad q0; 2,3 <- q0+128; 4,5 <- q0+256
    unsigned long long acc[8][6];
    {
        float4 b0 = *(const float4*)&bih[q0];
        float4 b1 = *(const float4*)&bih[q0 + 128];
        float4 b2 = *(const float4*)&bih[q0 + 256];
        unsigned long long p[6];
        PK2(p[0], b0.x, b0.y); PK2(p[1], b0.z, b0.w);
        PK2(p[2], b1.x, b1.y); PK2(p[3], b1.z, b1.w);
        PK2(p[4], b2.x, b2.y); PK2(p[5], b2.z, b2.w);
        #pragma unroll
        for (int i = 0; i < 8; i++)
            #pragma unroll
            for (int j = 0; j < 6; j++) acc[i][j] = p[j];
    }

    #pragma unroll 4
    for (int k = 0; k < DP; k++) {
        ulonglong2 w0 = *(const ulonglong2*)&ws[k * WSP + q0];
        ulonglong2 w1 = *(const ulonglong2*)&ws[k * WSP + q0 + 128];
        ulonglong2 w2 = *(const ulonglong2*)&ws[k * WSP + q0 + 256];
        float4 ha = *(const float4*)&hsT[k * HSP + r0];
        float4 hb = *(const float4*)&hsT[k * HSP + r0 + 4];
        float hv[8] = {ha.x, ha.y, ha.z, ha.w, hb.x, hb.y, hb.z, hb.w};
        #pragma unroll
        for (int i = 0; i < 8; i++) {
            unsigned long long hd;
            DUP2(hd, hv[i]);
            FMA2(acc[i][0], hd, w0.x); FMA2(acc[i][1], hd, w0.y);
            FMA2(acc[i][2], hd, w1.x); FMA2(acc[i][3], hd, w1.y);
            FMA2(acc[i][4], hd, w2.x); FMA2(acc[i][5], hd, w2.y);
        }
    }

    #pragma unroll
    for (int i = 0; i < 8; i++) {
        size_t base = (size_t)(R0 + r0 + i) * G3;
        float f0, f1, f2, f3;
        UPK2(f0, f1, acc[i][0]); UPK2(f2, f3, acc[i][1]);
        *(float4*)&g_xproj[base + q0] = make_float4(f0, f1, f2, f3);
        UPK2(f0, f1, acc[i][2]); UPK2(f2, f3, acc[i][3]);
        *(float4*)&g_xproj[base + q0 + 128] = make_float4(f0, f1, f2, f3);
        UPK2(f0, f1, acc[i][4]); UPK2(f2, f3, acc[i][5]);
        *(float4*)&g_xproj[base + q0 + 256] = make_float4(f0, f1, f2, f3);
    }
}

// ---------------------------------------------------------------------------
// Phase 2: GRU recurrence. One CTA = 4 batch rows, 512 threads (16 warps).
// Thread = 3 gate rows (j0, j0+128, j0+256) x 4 batches x 32-k quarter (kq).
// Accumulators packed over batch pairs (b0,b1),(b2,b3) via fma.rn.f32x2;
// h_s[k][4] layout makes both packed h operands one LDS.128.
// W for gates 0,1 register-resident (time-invariant); gate 2 from SMEM.
// ---------------------------------------------------------------------------
#define SM_W2   0                    // W_s2: [128][128]  (k-major, gate rows 256..383)
#define SM_HS   (HH * HH)            // h_s:  [128][4]
#define SM_GH   (SM_HS + HH * 4)     // gh_s: [4 kq][4 b][384]
#define SM_TOT  (SM_GH + 16 * G3)    // floats = 22656 (90,624 B)

__global__ __launch_bounds__(512, 1) void gru_kernel(
    const float* __restrict__ Whh,
    const float* __restrict__ bhh,
    const float* __restrict__ h0,
    float* __restrict__ out)
{
    extern __shared__ float smem[];
    float* W_s2 = smem + SM_W2;
    float* h_s  = smem + SM_HS;
    float* gh_s = smem + SM_GH;

    const int tid = threadIdx.x;
    const int bbase = blockIdx.x * 4;

    const int j0 = tid & 127;         // gate triple base: rows j0, j0+128, j0+256
    const int kq = tid >> 7;          // k quarter (0..3)
    const int kbase = kq * 32;

    // Register-resident W for gates 0,1: W[j][kbase..kbase+32)
    float Wr0[32], Wr1[32];
    #pragma unroll
    for (int q = 0; q < 8; q++) {
        *(float4*)&Wr0[q * 4] = *(const float4*)&Whh[(size_t)j0 * HH + kbase + q * 4];
        *(float4*)&Wr1[q * 4] = *(const float4*)&Whh[(size_t)(j0 + 128) * HH + kbase + q * 4];
    }
    // Gate-2 W -> SMEM k-major (one-time)
    for (int i = tid; i < HH * HH; i += 512) {
        int r = i >> 7, k = i & 127;            // gate row 256+r
        W_s2[k * HH + r] = Whh[(size_t)(256 + r) * HH + k];
    }
    // h0 broadcast over 4 batches, layout h_s[k][b]
    for (int i = tid; i < HH; i += 512) {
        float v = h0[i];
        *(float4*)&h_s[i * 4] = make_float4(v, v, v, v);
    }

    // Gate-phase mapping: thread -> (b = kq, hid = j0); bias applied there.
    const int hid = j0;
    const int b   = kq;
    const float br = bhh[hid], bz = bhh[hid + 128], bn = bhh[hid + 256];
    const float* xp = g_xproj + (size_t)(bbase + b) * TT * G3 + hid;
    float cxr = xp[0], cxz = xp[HH], cxn = xp[2 * HH];
    __syncthreads();

    for (int t = 0; t < TT; t++) {
        // Prefetch next step's x_proj (latency hidden behind k-loop)
        float nxr = 0, nxz = 0, nxn = 0;
        if (t + 1 < TT) {
            const float* p = xp + (size_t)(t + 1) * G3;
            nxr = p[0]; nxz = p[HH]; nxn = p[2 * HH];
        }

        unsigned long long a01[3] = {0ull, 0ull, 0ull};   // (b0,b1) per gate
        unsigned long long a23[3] = {0ull, 0ull, 0ull};   // (b2,b3) per gate

        #pragma unroll
        for (int i = 0; i < 32; i++) {
            const int k = kbase + i;
            ulonglong2 hp = *(const ulonglong2*)&h_s[k * 4];
            float w2 = W_s2[k * HH + j0];
            unsigned long long wd0, wd1, wd2;
            DUP2(wd0, Wr0[i]); DUP2(wd1, Wr1[i]); DUP2(wd2, w2);
            FMA2(a01[0], wd0, hp.x); FMA2(a23[0], wd0, hp.y);
            FMA2(a01[1], wd1, hp.x); FMA2(a23[1], wd1, hp.y);
            FMA2(a01[2], wd2, hp.x); FMA2(a23[2], wd2, hp.y);
        }

        #pragma unroll
        for (int g = 0; g < 3; g++) {
            const int jg = j0 + g * 128;
            float v0, v1, v2, v3;
            UPK2(v0, v1, a01[g]);
            UPK2(v2, v3, a23[g]);
            gh_s[(kq * 4 + 0) * G3 + jg] = v0;
            gh_s[(kq * 4 + 1) * G3 + jg] = v1;
            gh_s[(kq * 4 + 2) * G3 + jg] = v2;
            gh_s[(kq * 4 + 3) * G3 + jg] = v3;
        }
        __syncthreads();

        // Gate phase: 512 threads = 4 batches x 128 hid
        {
            float gr = br + gh_s[(0 + b) * G3 + hid]        + gh_s[(4 + b) * G3 + hid]
                          + gh_s[(8 + b) * G3 + hid]        + gh_s[(12 + b) * G3 + hid];
            float gz = bz + gh_s[(0 + b) * G3 + 128 + hid]  + gh_s[(4 + b) * G3 + 128 + hid]
                          + gh_s[(8 + b) * G3 + 128 + hid]  + gh_s[(12 + b) * G3 + 128 + hid];
            float gn = bn + gh_s[(0 + b) * G3 + 256 + hid]  + gh_s[(4 + b) * G3 + 256 + hid]
                          + gh_s[(8 + b) * G3 + 256 + hid]  + gh_s[(12 + b) * G3 + 256 + hid];
            float r = __fdividef(1.f, 1.f + __expf(-(cxr + gr)));
            float z = __fdividef(1.f, 1.f + __expf(-(cxz + gz)));
            float na = cxn + r * gn;
            float ea = __expf(-2.f * fabsf(na));
            float n  = copysignf(__fdividef(1.f - ea, 1.f + ea), na);
            float hold = h_s[hid * 4 + b];
            h_s[hid * 4 + b] = n + z * (hold - n);
            cxr = nxr; cxz = nxz; cxn = nxn;
        }
        __syncthreads();
    }

    out[(bbase + b) * HH + hid] = h_s[hid * 4 + b];
}

extern "C" void kernel_launch(void* const* d_in, const int* in_sizes, int n_in,
                              void* d_out, int out_size) {
    const float* hist = (const float*)d_in[0];
    const float* Wih  = (const float*)d_in[1];
    const float* Whh  = (const float*)d_in[2];
    const float* bih  = (const float*)d_in[3];
    const float* bhh  = (const float*)d_in[4];
    const float* h0   = (const float*)d_in[5];
    float* out = (float*)d_out;

    const size_t xsm_bytes = (size_t)(DP * HSP + DP * WSP) * sizeof(float); // 87,552
    cudaFuncSetAttribute(xproj_kernel, cudaFuncAttributeMaxDynamicSharedMemorySize,
                         (int)xsm_bytes);
    xproj_kernel<<<BT / 64, 256, xsm_bytes>>>(hist, Wih, bih);

    const size_t smem_bytes = (size_t)SM_TOT * sizeof(float);  // 90,624 B
    cudaFuncSetAttribute(gru_kernel, cudaFuncAttributeMaxDynamicSharedMemorySize,
                         (int)smem_bytes);
    gru_kernel<<<BB / 4, 512, smem_bytes>>>(Whh, bhh, h0, out);
}